// round 10
// baseline (speedup 1.0000x reference)
#include <cuda_runtime.h>
#include <cstdint>

// Problem dims (fixed by reference setup_inputs)
#define TB 4      // batch
#define TT 512    // tokens
#define TD 1024   // d_model
#define TNC 16    // n_concepts
#define TH 256    // init_size
#define NBATCH (TB * TNC)   // 64 batched GEMMs

// ---------------- scratch (__device__ globals; allocation-free rule) ----------------
__device__ float g_wq[(size_t)NBATCH * TT * TH];      // fp32 wq[z][t][h]
__device__ float g_attn_fb[(size_t)NBATCH * TT * TT]; // fp32 attn if d_out has no slot

// ---------------- helpers ----------------
// bf16 hi/lo split of a k-adjacent fp32 pair -> packed bf16x2 regs (lo half = even k)
__device__ __forceinline__ void bf16_pack_split(float f0, float f1, uint32_t& hi, uint32_t& lo) {
    uint32_t h;
    asm("cvt.rn.bf16x2.f32 %0, %1, %2;" : "=r"(h) : "f"(f1), "f"(f0));  // hi-half=f1, lo-half=f0
    const float h0 = __uint_as_float(h << 16);
    const float h1 = __uint_as_float(h & 0xFFFF0000u);
    const float l0 = f0 - h0;
    const float l1 = f1 - h1;
    asm("cvt.rn.bf16x2.f32 %0, %1, %2;" : "=r"(lo) : "f"(l1), "f"(l0));
    hi = h;
}
__device__ __forceinline__ void mma_bf16(float* d, const uint32_t* a, const uint32_t* b) {
    asm volatile(
        "mma.sync.aligned.m16n8k16.row.col.f32.bf16.bf16.f32 "
        "{%0,%1,%2,%3}, {%4,%5,%6,%7}, {%8,%9}, {%0,%1,%2,%3};"
        : "+f"(d[0]), "+f"(d[1]), "+f"(d[2]), "+f"(d[3])
        : "r"(a[0]), "r"(a[1]), "r"(a[2]), "r"(a[3]), "r"(b[0]), "r"(b[1]));
}

// ---------------- bf16x3 batched GEMM: C tile 128x128 = A[M,K] * B(k,n) ----------------
// SMEM holds PRE-SPLIT packed bf16x2 hi/lo words (split once per CTA during staging;
// staging = LDG->reg->split->STS, the pattern proven by the passing R7 kernel).
// Packed layouts (word [m][k2] = bf16x2 of k=2*k2, 2*k2+1):
//   pA   [2][128][10]  (pad 10 -> conflict-free LDS.32 fragment loads)
//   pB   direct modes: [2][8][132]  ([k2][n]);  BTR mode 2: [2][128][10]  ([n][k2])
// Double-buffered, ONE __syncthreads per K-block; LDG prefetch hides under MMAs.
template <int MODE>
__global__ __launch_bounds__(256, 2) void k_gemm_bf16(const float* __restrict__ Ain,
                                                      const float* __restrict__ Bin,
                                                      float* __restrict__ Cout) {
    constexpr int K   = (MODE == 1) ? TD : (MODE == 2) ? TH : TT;
    constexpr int NKB = K / 16;
    constexpr int LDA = K;
    constexpr int LDB = (MODE == 1) ? TH : (MODE == 2) ? TH : TD;
    constexpr int LDC = (MODE == 1) ? TH : (MODE == 2) ? TT : TD;
    constexpr bool BTR = (MODE == 2);          // B stored [n][k]
    constexpr int BR = BTR ? 128 : 8;
    constexpr int BC = BTR ? 10  : 132;

    __shared__ uint32_t pAhi[2][128][10], pAlo[2][128][10];
    __shared__ uint32_t pBhi[2][BR][BC],  pBlo[2][BR][BC];

    const int tid = threadIdx.x, wid = tid >> 5, lane = tid & 31;
    const int wm = wid & 1, wn = wid >> 1;     // 2x4 warp grid, warp tile 64x32
    const int lr = lane >> 2, lq = lane & 3;
    const int z = blockIdx.z;
    const int m0 = blockIdx.y * 128;
    const int n0 = blockIdx.x * 128;

    size_t aoff, boff;
    if constexpr (MODE == 1) {
        aoff = (size_t)(z >> 4) * TT * TD;
        boff = (size_t)(z & 15) * TD * TH;
    } else if constexpr (MODE == 2) {
        aoff = (size_t)z * TT * TH;
        boff = aoff;
    } else {
        aoff = (size_t)z * TT * TT;
        boff = (size_t)(z >> 4) * TT * TD;
    }
    const float* pA_ = Ain + aoff + (size_t)m0 * LDA;
    const float* pB_ = BTR ? (Bin + boff + (size_t)n0 * LDB)   // [n][k] row offset
                           : (Bin + boff + n0);                // [k][n] col offset

    float acc[4][4][4];
#pragma unroll
    for (int mi = 0; mi < 4; mi++)
#pragma unroll
        for (int ni = 0; ni < 4; ni++)
#pragma unroll
            for (int e = 0; e < 4; e++) acc[mi][ni][e] = 0.0f;

    // ---- staging: LDG prefetch into regs, then split+STS packed hi/lo ----
    float4 pfA[2], pfB[2];
    auto prefetch = [&](int kb) {
#pragma unroll
        for (int i = 0; i < 2; i++) {
            const int cid = tid + i * 256;
            const int ar = cid >> 2, ac4 = cid & 3;
            pfA[i] = *reinterpret_cast<const float4*>(pA_ + (size_t)ar * LDA + kb * 16 + ac4 * 4);
        }
        if constexpr (BTR) {
#pragma unroll
            for (int i = 0; i < 2; i++) {
                const int cid = tid + i * 256;
                const int nr = cid >> 2, kc4 = cid & 3;
                pfB[i] = *reinterpret_cast<const float4*>(pB_ + (size_t)nr * LDB + kb * 16 + kc4 * 4);
            }
        } else {
            const int j = tid >> 5, nc = tid & 31;   // rows 2j,2j+1 ; n-chunk nc
            pfB[0] = *reinterpret_cast<const float4*>(pB_ + (size_t)(kb * 16 + 2 * j) * LDB + nc * 4);
            pfB[1] = *reinterpret_cast<const float4*>(pB_ + (size_t)(kb * 16 + 2 * j + 1) * LDB + nc * 4);
        }
    };
    auto store_stage = [&](int s) {
#pragma unroll
        for (int i = 0; i < 2; i++) {
            const int cid = tid + i * 256;
            const int ar = cid >> 2, ac4 = cid & 3;
            uint32_t h0, l0, h1, l1;
            bf16_pack_split(pfA[i].x, pfA[i].y, h0, l0);
            bf16_pack_split(pfA[i].z, pfA[i].w, h1, l1);
            *reinterpret_cast<uint2*>(&pAhi[s][ar][ac4 * 2]) = make_uint2(h0, h1);
            *reinterpret_cast<uint2*>(&pAlo[s][ar][ac4 * 2]) = make_uint2(l0, l1);
        }
        if constexpr (BTR) {
#pragma unroll
            for (int i = 0; i < 2; i++) {
                const int cid = tid + i * 256;
                const int nr = cid >> 2, kc4 = cid & 3;
                uint32_t h0, l0, h1, l1;
                bf16_pack_split(pfB[i].x, pfB[i].y, h0, l0);
                bf16_pack_split(pfB[i].z, pfB[i].w, h1, l1);
                *reinterpret_cast<uint2*>(&pBhi[s][nr][kc4 * 2]) = make_uint2(h0, h1);
                *reinterpret_cast<uint2*>(&pBlo[s][nr][kc4 * 2]) = make_uint2(l0, l1);
            }
        } else {
            const int j = tid >> 5, nc = tid & 31;
            uint32_t bh4[4], bl4[4];
            bf16_pack_split(pfB[0].x, pfB[1].x, bh4[0], bl4[0]);
            bf16_pack_split(pfB[0].y, pfB[1].y, bh4[1], bl4[1]);
            bf16_pack_split(pfB[0].z, pfB[1].z, bh4[2], bl4[2]);
            bf16_pack_split(pfB[0].w, pfB[1].w, bh4[3], bl4[3]);
            *reinterpret_cast<uint4*>(&pBhi[s][j][nc * 4]) = make_uint4(bh4[0], bh4[1], bh4[2], bh4[3]);
            *reinterpret_cast<uint4*>(&pBlo[s][j][nc * 4]) = make_uint4(bl4[0], bl4[1], bl4[2], bl4[3]);
        }
    };

    prefetch(0);
    store_stage(0);
    __syncthreads();

#pragma unroll 1
    for (int kb = 0; kb < NKB; kb++) {
        const int s = kb & 1;
        if (kb + 1 < NKB) prefetch(kb + 1);   // LDG latency hides under MMAs below

        // ---- fragment loads: bare LDS.32 from packed hi/lo (no split math) ----
        uint32_t ah[4][4], al[4][4], bh[4][2], bl[4][2];
#pragma unroll
        for (int mi = 0; mi < 4; mi++) {
            const int row = wm * 64 + mi * 16 + lr;
            ah[mi][0] = pAhi[s][row][lq];         al[mi][0] = pAlo[s][row][lq];
            ah[mi][1] = pAhi[s][row + 8][lq];     al[mi][1] = pAlo[s][row + 8][lq];
            ah[mi][2] = pAhi[s][row][lq + 4];     al[mi][2] = pAlo[s][row][lq + 4];
            ah[mi][3] = pAhi[s][row + 8][lq + 4]; al[mi][3] = pAlo[s][row + 8][lq + 4];
        }
#pragma unroll
        for (int ni = 0; ni < 4; ni++) {
            const int n = wn * 32 + ni * 8 + lr;
            if constexpr (BTR) {
                bh[ni][0] = pBhi[s][n][lq];     bl[ni][0] = pBlo[s][n][lq];
                bh[ni][1] = pBhi[s][n][lq + 4]; bl[ni][1] = pBlo[s][n][lq + 4];
            } else {
                bh[ni][0] = pBhi[s][lq][n];     bl[ni][0] = pBlo[s][lq][n];
                bh[ni][1] = pBhi[s][lq + 4][n]; bl[ni][1] = pBlo[s][lq + 4][n];
            }
        }

        // pass-major MMA ordering: dependent acc updates are 16 MMAs apart
#pragma unroll
        for (int mi = 0; mi < 4; mi++)
#pragma unroll
            for (int ni = 0; ni < 4; ni++)
                mma_bf16(acc[mi][ni], ah[mi], bh[ni]);   // hi*hi
#pragma unroll
        for (int mi = 0; mi < 4; mi++)
#pragma unroll
            for (int ni = 0; ni < 4; ni++)
                mma_bf16(acc[mi][ni], ah[mi], bl[ni]);   // hi*lo
#pragma unroll
        for (int mi = 0; mi < 4; mi++)
#pragma unroll
            for (int ni = 0; ni < 4; ni++)
                mma_bf16(acc[mi][ni], al[mi], bh[ni]);   // lo*hi

        if (kb + 1 < NKB) store_stage(s ^ 1);  // safe: stage s^1 readers done at kb-1's sync
        __syncthreads();
    }

    // ---- epilogue: fp32 float2 stores (identical to passing R9) ----
    const int rbase = m0 + wm * 64 + lr;
    const int cbase = n0 + wn * 32 + lq * 2;
#pragma unroll
    for (int mi = 0; mi < 4; mi++)
#pragma unroll
        for (int ni = 0; ni < 4; ni++)
#pragma unroll
            for (int h = 0; h < 2; h++) {
                const int row = rbase + mi * 16 + h * 8;
                const int col = cbase + ni * 8;
                float* dst = Cout + (size_t)z * TT * LDC + (size_t)row * LDC + col;
                *reinterpret_cast<float2*>(dst) =
                    make_float2(acc[mi][ni][2 * h], acc[mi][ni][2 * h + 1]);
            }
}

// ---------------- softmax over rows of 512 (unchanged, passing) ----------------
__global__ __launch_bounds__(256) void k_softmax(float* __restrict__ attn) {
    __shared__ float redm[8];
    __shared__ float reds[8];
    float* p = attn + (size_t)blockIdx.x * TT;
    const int tid = threadIdx.x;

    float v0 = p[tid];
    float v1 = p[tid + 256];
    float m = fmaxf(v0, v1);
#pragma unroll
    for (int o = 16; o; o >>= 1) m = fmaxf(m, __shfl_xor_sync(0xffffffffu, m, o));
    if ((tid & 31) == 0) redm[tid >> 5] = m;
    __syncthreads();
    float mAll = redm[0];
#pragma unroll
    for (int w = 1; w < 8; w++) mAll = fmaxf(mAll, redm[w]);

    float e0 = expf(v0 - mAll);
    float e1 = expf(v1 - mAll);
    float s = e0 + e1;
#pragma unroll
    for (int o = 16; o; o >>= 1) s += __shfl_xor_sync(0xffffffffu, s, o);
    if ((tid & 31) == 0) reds[tid >> 5] = s;
    __syncthreads();
    float sAll = 0.0f;
#pragma unroll
    for (int w = 0; w < 8; w++) sAll += reds[w];
    const float inv = 1.0f / sAll;
    p[tid] = e0 * inv;
    p[tid + 256] = e1 * inv;
}

// ---------------- launcher (unchanged, passing) ----------------
extern "C" void kernel_launch(void* const* d_in, const int* in_sizes, int n_in,
                              void* d_out, int out_size) {
    (void)in_sizes; (void)n_in;
    const float* x   = (const float*)d_in[0];
    const float* wqs = (const float*)d_in[1];
    // d_in[2] = w_ks: unused in reference math (faithful to source bug)
    float* out = (float*)d_out;

    const long long EAGG = (long long)NBATCH * TT * TD;  // 33,554,432
    const long long ATTN = (long long)NBATCH * TT * TT;  // 16,777,216

    float* attn;
    if ((long long)out_size >= EAGG + ATTN) {
        attn = out + EAGG;
    } else {
        void* p = nullptr;
        cudaGetSymbolAddress(&p, g_attn_fb);
        attn = (float*)p;
    }
    void* wqp = nullptr;
    cudaGetSymbolAddress(&wqp, g_wq);
    float* wq = (float*)wqp;

    // GEMM1: wq = x @ w_qs
    k_gemm_bf16<1><<<dim3(TH / 128, TT / 128, NBATCH), 256>>>(x, wqs, wq);
    // GEMM2: logits = wq @ wq^T
    k_gemm_bf16<2><<<dim3(TT / 128, TT / 128, NBATCH), 256>>>(wq, wq, attn);
    // softmax in place
    k_softmax<<<NBATCH * TT, 256>>>(attn);
    // GEMM3: e = attn @ x
    k_gemm_bf16<3><<<dim3(TD / 128, TT / 128, NBATCH), 256>>>(attn, x, out);
}